// round 2
// baseline (speedup 1.0000x reference)
#include <cuda_runtime.h>
#include <cstdint>
#include <cstddef>

// Problem dims (fixed by the dataset)
#define NQ 8192     // batch rows
#define MC 20000    // centers
#define MP 20096    // centers padded to multiple of 128 (157 * 128)
#define DD 1024     // feature dim
#define YY 256      // output dim
#define PADA 20     // smem row stride (words) for k-contiguous tiles (conflict-free: 20 mod 32 walk)
#define PADB 136    // smem row stride (words) for W tile (136 mod 32 = 8 -> conflict-free b-frag reads)

// Scratch: K matrix (fp32), row-sq norms. __device__ globals are the allowed scratch mechanism.
__device__ float g_K[(size_t)NQ * MP];
__device__ float g_xsq[NQ];
__device__ float g_zsq[MP];   // zero-initialized at module load; padding [MC, MP) stays 0

// ---------------------------------------------------------------------------
// Helpers
// ---------------------------------------------------------------------------
__device__ __forceinline__ uint32_t f2tf(float f) {
    uint32_t r;
    asm("cvt.rna.tf32.f32 %0, %1;" : "=r"(r) : "f"(f));  // round-to-nearest: unbiased (RZ would bias -1e-3)
    return r;
}

__device__ __forceinline__ void mma_tf32(float* c, const uint32_t* a, const uint32_t* b) {
    asm volatile(
        "mma.sync.aligned.m16n8k8.row.col.f32.tf32.tf32.f32 "
        "{%0,%1,%2,%3},{%4,%5,%6,%7},{%8,%9},{%0,%1,%2,%3};"
        : "+f"(c[0]), "+f"(c[1]), "+f"(c[2]), "+f"(c[3])
        : "r"(a[0]), "r"(a[1]), "r"(a[2]), "r"(a[3]), "r"(b[0]), "r"(b[1]));
}

// bandwidth arrives as a 1-element device buffer of unknown int32/float32 dtype; hedge both.
__device__ __forceinline__ float resolve_bw(const void* p) {
    int iv = *(const int*)p;
    if (iv > 0 && iv < 1000000) return (float)iv;   // int32 payload
    return *(const float*)p;                        // float32 payload
}

// ---------------------------------------------------------------------------
// Kernel 0: row squared norms for batch (-> g_xsq) and centers (-> g_zsq)
// One warp per row. 28192 warps total.
// ---------------------------------------------------------------------------
__global__ void rowsq_kernel(const float* __restrict__ x, const float* __restrict__ z) {
    int gwarp = (blockIdx.x * blockDim.x + threadIdx.x) >> 5;
    int lane = threadIdx.x & 31;
    const float* src;
    float* dst;
    if (gwarp < NQ)            { src = x + (size_t)gwarp * DD;        dst = g_xsq + gwarp; }
    else if (gwarp < NQ + MC)  { int r = gwarp - NQ;
                                 src = z + (size_t)r * DD;            dst = g_zsq + r; }
    else return;
    const float4* p = (const float4*)src;
    float s = 0.f;
#pragma unroll
    for (int i = 0; i < DD / 128; i++) {
        float4 v = p[lane + i * 32];
        s += v.x * v.x + v.y * v.y + v.z * v.z + v.w * v.w;
    }
#pragma unroll
    for (int o = 16; o; o >>= 1) s += __shfl_xor_sync(0xffffffffu, s, o);
    if (lane == 0) *dst = s;
}

// ---------------------------------------------------------------------------
// Kernel 1: K[i,j] = exp(-sqrt(max(xsq[i]+zsq[j]-2*X[i,:].Z[j,:], 0))/bw)
// Tiled NT GEMM (both operands k-contiguous), tf32 mma, BM=BN=128, BK=16.
// 8 warps: warp tile 64x32 (wm in {0,1} x64, wn in {0..3} x32).
// Grid: (64, 157). Writes padded K (garbage in padded cols, never read).
// ---------------------------------------------------------------------------
__global__ __launch_bounds__(256, 2)
void laplace_gemm_kernel(const float* __restrict__ X, const float* __restrict__ Z,
                         const void* __restrict__ bwp) {
    __shared__ uint32_t Xs[2][128][PADA];
    __shared__ uint32_t Zs[2][128][PADA];

    const int bm = blockIdx.x;      // 0..63  (rows of X)
    const int bn = blockIdx.y;      // 0..156 (rows of Z)
    const int tid = threadIdx.x;
    const int lane = tid & 31;
    const int wid = tid >> 5;
    const int wm = (wid & 1) * 64;
    const int wn = (wid >> 1) * 32;

    float acc[4][4][4];
#pragma unroll
    for (int mt = 0; mt < 4; mt++)
#pragma unroll
        for (int nt = 0; nt < 4; nt++)
#pragma unroll
            for (int i = 0; i < 4; i++) acc[mt][nt][i] = 0.f;

    // Global staging addressing: thread covers rows lr and lr+64, 4 k-cols at lc.
    const int lr = tid >> 2;             // 0..63
    const int lc = (tid & 3) << 2;       // 0,4,8,12
    const size_t xbase0 = (size_t)(bm * 128 + lr) * DD + lc;
    const size_t xbase1 = xbase0 + (size_t)64 * DD;
    const int zr0 = bn * 128 + lr;
    const int zr1 = zr0 + 64;
    const size_t zbase0 = (size_t)zr0 * DD + lc;
    const size_t zbase1 = (size_t)zr1 * DD + lc;
    const bool zok0 = (zr0 < MC), zok1 = (zr1 < MC);

    // Prologue: load tile 0
    float4 x0 = *(const float4*)(X + xbase0);
    float4 x1 = *(const float4*)(X + xbase1);
    float4 z0 = zok0 ? *(const float4*)(Z + zbase0) : make_float4(0.f, 0.f, 0.f, 0.f);
    float4 z1 = zok1 ? *(const float4*)(Z + zbase1) : make_float4(0.f, 0.f, 0.f, 0.f);
    {
        uint4 u;
        u.x = f2tf(x0.x); u.y = f2tf(x0.y); u.z = f2tf(x0.z); u.w = f2tf(x0.w);
        *(uint4*)&Xs[0][lr][lc] = u;
        u.x = f2tf(x1.x); u.y = f2tf(x1.y); u.z = f2tf(x1.z); u.w = f2tf(x1.w);
        *(uint4*)&Xs[0][lr + 64][lc] = u;
        u.x = f2tf(z0.x); u.y = f2tf(z0.y); u.z = f2tf(z0.z); u.w = f2tf(z0.w);
        *(uint4*)&Zs[0][lr][lc] = u;
        u.x = f2tf(z1.x); u.y = f2tf(z1.y); u.z = f2tf(z1.z); u.w = f2tf(z1.w);
        *(uint4*)&Zs[0][lr + 64][lc] = u;
    }
    __syncthreads();

    const int KT = DD / 16;   // 64
    for (int kt = 0; kt < KT; kt++) {
        const int buf = kt & 1;
        float4 nx0, nx1, nz0, nz1;
        if (kt + 1 < KT) {
            size_t off = (size_t)(kt + 1) * 16;
            nx0 = *(const float4*)(X + xbase0 + off);
            nx1 = *(const float4*)(X + xbase1 + off);
            nz0 = zok0 ? *(const float4*)(Z + zbase0 + off) : make_float4(0.f, 0.f, 0.f, 0.f);
            nz1 = zok1 ? *(const float4*)(Z + zbase1 + off) : make_float4(0.f, 0.f, 0.f, 0.f);
        }

#pragma unroll
        for (int kk = 0; kk < 2; kk++) {
            const int k0 = kk * 8 + (lane & 3);
            const int frow = lane >> 2;
            uint32_t a[4][4], b[4][2];
#pragma unroll
            for (int mt = 0; mt < 4; mt++) {
                int r = wm + mt * 16 + frow;
                a[mt][0] = Xs[buf][r][k0];
                a[mt][1] = Xs[buf][r + 8][k0];
                a[mt][2] = Xs[buf][r][k0 + 4];
                a[mt][3] = Xs[buf][r + 8][k0 + 4];
            }
#pragma unroll
            for (int nt = 0; nt < 4; nt++) {
                int r = wn + nt * 8 + frow;
                b[nt][0] = Zs[buf][r][k0];
                b[nt][1] = Zs[buf][r][k0 + 4];
            }
#pragma unroll
            for (int mt = 0; mt < 4; mt++)
#pragma unroll
                for (int nt = 0; nt < 4; nt++)
                    mma_tf32(acc[mt][nt], a[mt], b[nt]);
        }

        if (kt + 1 < KT) {
            const int nb = buf ^ 1;
            uint4 u;
            u.x = f2tf(nx0.x); u.y = f2tf(nx0.y); u.z = f2tf(nx0.z); u.w = f2tf(nx0.w);
            *(uint4*)&Xs[nb][lr][lc] = u;
            u.x = f2tf(nx1.x); u.y = f2tf(nx1.y); u.z = f2tf(nx1.z); u.w = f2tf(nx1.w);
            *(uint4*)&Xs[nb][lr + 64][lc] = u;
            u.x = f2tf(nz0.x); u.y = f2tf(nz0.y); u.z = f2tf(nz0.z); u.w = f2tf(nz0.w);
            *(uint4*)&Zs[nb][lr][lc] = u;
            u.x = f2tf(nz1.x); u.y = f2tf(nz1.y); u.z = f2tf(nz1.z); u.w = f2tf(nz1.w);
            *(uint4*)&Zs[nb][lr + 64][lc] = u;
        }
        __syncthreads();
    }

    // Epilogue: d2 -> exp(-d/bw) -> K (padded stride, no col bounds needed)
    const float inv_bw = 1.0f / resolve_bw(bwp);
#pragma unroll
    for (int mt = 0; mt < 4; mt++) {
        const int r0 = bm * 128 + wm + mt * 16 + (lane >> 2);
        const float xs0 = g_xsq[r0];
        const float xs1 = g_xsq[r0 + 8];
#pragma unroll
        for (int nt = 0; nt < 4; nt++) {
            const int c0 = bn * 128 + wn + nt * 8 + ((lane & 3) << 1);
            const float zs0 = g_zsq[c0];
            const float zs1 = g_zsq[c0 + 1];
            float2 v;
            v.x = __expf(-sqrtf(fmaxf(xs0 + zs0 - 2.f * acc[mt][nt][0], 0.f)) * inv_bw);
            v.y = __expf(-sqrtf(fmaxf(xs0 + zs1 - 2.f * acc[mt][nt][1], 0.f)) * inv_bw);
            *(float2*)&g_K[(size_t)r0 * MP + c0] = v;
            v.x = __expf(-sqrtf(fmaxf(xs1 + zs0 - 2.f * acc[mt][nt][2], 0.f)) * inv_bw);
            v.y = __expf(-sqrtf(fmaxf(xs1 + zs1 - 2.f * acc[mt][nt][3], 0.f)) * inv_bw);
            *(float2*)&g_K[(size_t)(r0 + 8) * MP + c0] = v;
        }
    }
}

// ---------------------------------------------------------------------------
// Kernel 2: pred = K @ W.  NN GEMM, K row-major (stride MP), W [MC, YY] row-major.
// BM=128, BN=128, BK=16, grid (64, 2). k-loop 20000/16 = 1250 iterations.
// ---------------------------------------------------------------------------
__global__ __launch_bounds__(256, 2)
void wgemm_kernel(const float* __restrict__ W, float* __restrict__ out) {
    __shared__ uint32_t As[2][128][PADA];
    __shared__ uint32_t Bs[2][16][PADB];

    const int bm = blockIdx.x;   // 0..63
    const int bn = blockIdx.y;   // 0..1
    const int tid = threadIdx.x;
    const int lane = tid & 31;
    const int wid = tid >> 5;
    const int wm = (wid & 1) * 64;
    const int wn = (wid >> 1) * 32;

    float acc[4][4][4];
#pragma unroll
    for (int mt = 0; mt < 4; mt++)
#pragma unroll
        for (int nt = 0; nt < 4; nt++)
#pragma unroll
            for (int i = 0; i < 4; i++) acc[mt][nt][i] = 0.f;

    // A (K-matrix) staging: rows lr, lr+64; 4 k-cols at lc
    const int lr = tid >> 2;
    const int lc = (tid & 3) << 2;
    const size_t abase0 = (size_t)(bm * 128 + lr) * MP + lc;
    const size_t abase1 = abase0 + (size_t)64 * MP;
    // B (W) staging: rows kb, kb+8 of the 16-row k-slab; 4 n-cols at nb
    const int kb = tid >> 5;             // 0..7
    const int nb = (tid & 31) << 2;      // 0..124
    const size_t bbase0 = (size_t)kb * YY + bn * 128 + nb;
    const size_t bbase1 = bbase0 + (size_t)8 * YY;

    // Prologue
    float4 a0 = *(const float4*)(g_K + abase0);
    float4 a1 = *(const float4*)(g_K + abase1);
    float4 b0 = *(const float4*)(W + bbase0);
    float4 b1 = *(const float4*)(W + bbase1);
    {
        uint4 u;
        u.x = f2tf(a0.x); u.y = f2tf(a0.y); u.z = f2tf(a0.z); u.w = f2tf(a0.w);
        *(uint4*)&As[0][lr][lc] = u;
        u.x = f2tf(a1.x); u.y = f2tf(a1.y); u.z = f2tf(a1.z); u.w = f2tf(a1.w);
        *(uint4*)&As[0][lr + 64][lc] = u;
        u.x = f2tf(b0.x); u.y = f2tf(b0.y); u.z = f2tf(b0.z); u.w = f2tf(b0.w);
        *(uint4*)&Bs[0][kb][nb] = u;
        u.x = f2tf(b1.x); u.y = f2tf(b1.y); u.z = f2tf(b1.z); u.w = f2tf(b1.w);
        *(uint4*)&Bs[0][kb + 8][nb] = u;
    }
    __syncthreads();

    const int KT = MC / 16;   // 1250
    for (int kt = 0; kt < KT; kt++) {
        const int buf = kt & 1;
        float4 na0, na1, nb0, nb1;
        if (kt + 1 < KT) {
            size_t aoff = (size_t)(kt + 1) * 16;
            size_t boff = (size_t)(kt + 1) * 16 * YY;
            na0 = *(const float4*)(g_K + abase0 + aoff);
            na1 = *(const float4*)(g_K + abase1 + aoff);
            nb0 = *(const float4*)(W + bbase0 + boff);
            nb1 = *(const float4*)(W + bbase1 + boff);
        }

#pragma unroll
        for (int kk = 0; kk < 2; kk++) {
            const int k0 = kk * 8 + (lane & 3);
            const int frow = lane >> 2;
            uint32_t a[4][4], b[4][2];
#pragma unroll
            for (int mt = 0; mt < 4; mt++) {
                int r = wm + mt * 16 + frow;
                a[mt][0] = As[buf][r][k0];
                a[mt][1] = As[buf][r + 8][k0];
                a[mt][2] = As[buf][r][k0 + 4];
                a[mt][3] = As[buf][r + 8][k0 + 4];
            }
#pragma unroll
            for (int nt = 0; nt < 4; nt++) {
                int c = wn + nt * 8 + frow;
                b[nt][0] = Bs[buf][k0][c];
                b[nt][1] = Bs[buf][k0 + 4][c];
            }
#pragma unroll
            for (int mt = 0; mt < 4; mt++)
#pragma unroll
                for (int nt = 0; nt < 4; nt++)
                    mma_tf32(acc[mt][nt], a[mt], b[nt]);
        }

        if (kt + 1 < KT) {
            const int nbuf = buf ^ 1;
            uint4 u;
            u.x = f2tf(na0.x); u.y = f2tf(na0.y); u.z = f2tf(na0.z); u.w = f2tf(na0.w);
            *(uint4*)&As[nbuf][lr][lc] = u;
            u.x = f2tf(na1.x); u.y = f2tf(na1.y); u.z = f2tf(na1.z); u.w = f2tf(na1.w);
            *(uint4*)&As[nbuf][lr + 64][lc] = u;
            u.x = f2tf(nb0.x); u.y = f2tf(nb0.y); u.z = f2tf(nb0.z); u.w = f2tf(nb0.w);
            *(uint4*)&Bs[nbuf][kb][nb] = u;
            u.x = f2tf(nb1.x); u.y = f2tf(nb1.y); u.z = f2tf(nb1.z); u.w = f2tf(nb1.w);
            *(uint4*)&Bs[nbuf][kb + 8][nb] = u;
        }
        __syncthreads();
    }

    // Epilogue: direct store to out
#pragma unroll
    for (int mt = 0; mt < 4; mt++) {
        const int r0 = bm * 128 + wm + mt * 16 + (lane >> 2);
#pragma unroll
        for (int nt = 0; nt < 4; nt++) {
            const int c0 = bn * 128 + wn + nt * 8 + ((lane & 3) << 1);
            *(float2*)(out + (size_t)r0 * YY + c0) =
                make_float2(acc[mt][nt][0], acc[mt][nt][1]);
            *(float2*)(out + (size_t)(r0 + 8) * YY + c0) =
                make_float2(acc[mt][nt][2], acc[mt][nt][3]);
        }
    }
}

// ---------------------------------------------------------------------------
// Entry point (graph-capturable: launches only, default stream ordering)
// ---------------------------------------------------------------------------
extern "C" void kernel_launch(void* const* d_in, const int* in_sizes, int n_in,
                              void* d_out, int out_size) {
    const float* batch   = (const float*)d_in[0];
    const float* centers = (const float*)d_in[1];
    const float* weight  = (const float*)d_in[2];
    const void*  bwp     = d_in[3];

    // 1) row squared norms
    {
        int warps = NQ + MC;                       // 28192
        int blocks = (warps * 32 + 255) / 256;     // 3524
        rowsq_kernel<<<blocks, 256>>>(batch, centers);
    }
    // 2) K = exp(-dist/bw)
    {
        dim3 grid(NQ / 128, (MC + 127) / 128);     // (64, 157)
        laplace_gemm_kernel<<<grid, 256>>>(batch, centers, bwp);
    }
    // 3) pred = K @ W
    {
        dim3 grid(NQ / 128, YY / 128);             // (64, 2)
        wgemm_kernel<<<grid, 256>>>(weight, (float*)d_out);
    }
}

// round 6
// speedup vs baseline: 1.2886x; 1.2886x over previous
#include <cuda_runtime.h>
#include <cuda_fp16.h>
#include <cstdint>
#include <cstddef>

// Problem dims
#define NQ 8192
#define MC 20000
#define MP 20096            // centers padded: 157*128, divisible by 32
#define DD 1024
#define YY 256
#define PADW 20             // smem row stride in 32-bit words (conflict-free walk)

// Scratch (device globals: the allowed scratch mechanism; zero-init at load)
__device__ __half g_K[(size_t)NQ * MP];    // 329 MB fp16 kernel matrix
__device__ __half g_Wt[(size_t)YY * MP];   // W transposed, k-contiguous; tail [MC,MP) stays 0
__device__ float  g_xsq[NQ];
__device__ float  g_zsq[MP];               // tail stays 0

// ---------------------------------------------------------------------------
// Helpers
// ---------------------------------------------------------------------------
__device__ __forceinline__ void mma_f16(float* c, const uint32_t* a, const uint32_t* b) {
    asm volatile(
        "mma.sync.aligned.m16n8k16.row.col.f32.f16.f16.f32 "
        "{%0,%1,%2,%3},{%4,%5,%6,%7},{%8,%9},{%0,%1,%2,%3};"
        : "+f"(c[0]), "+f"(c[1]), "+f"(c[2]), "+f"(c[3])
        : "r"(a[0]), "r"(a[1]), "r"(a[2]), "r"(a[3]), "r"(b[0]), "r"(b[1]));
}

__device__ __forceinline__ uint32_t h2u(__half2 h) {
    return *reinterpret_cast<uint32_t*>(&h);
}

// bandwidth: 1-element buffer of unknown int32/float32 dtype; hedge both.
__device__ __forceinline__ float resolve_bw(const void* p) {
    int iv = *(const int*)p;
    if (iv > 0 && iv < 1000000) return (float)iv;
    return *(const float*)p;
}

// ---------------------------------------------------------------------------
// Kernel 0: row squared norms (one warp per row)
// ---------------------------------------------------------------------------
__global__ void rowsq_kernel(const float* __restrict__ x, const float* __restrict__ z) {
    int gwarp = (blockIdx.x * blockDim.x + threadIdx.x) >> 5;
    int lane = threadIdx.x & 31;
    const float* src;
    float* dst;
    if (gwarp < NQ)            { src = x + (size_t)gwarp * DD;  dst = g_xsq + gwarp; }
    else if (gwarp < NQ + MC)  { int r = gwarp - NQ;
                                 src = z + (size_t)r * DD;      dst = g_zsq + r; }
    else return;
    const float4* p = (const float4*)src;
    float s = 0.f;
#pragma unroll
    for (int i = 0; i < DD / 128; i++) {
        float4 v = p[lane + i * 32];
        s += v.x * v.x + v.y * v.y + v.z * v.z + v.w * v.w;
    }
#pragma unroll
    for (int o = 16; o; o >>= 1) s += __shfl_xor_sync(0xffffffffu, s, o);
    if (lane == 0) *dst = s;
}

// ---------------------------------------------------------------------------
// Kernel 0b: transpose W [MC, YY] fp32 -> g_Wt [YY, MP] fp16 (k-contiguous)
// 32x32 smem tile transpose. Grid (625, 8), block (32, 32).
// ---------------------------------------------------------------------------
__global__ void wtrans_kernel(const float* __restrict__ W) {
    __shared__ float t[32][33];
    const int k0 = blockIdx.x * 32;
    const int n0 = blockIdx.y * 32;
    const int tx = threadIdx.x, ty = threadIdx.y;
    t[ty][tx] = W[(size_t)(k0 + ty) * YY + (n0 + tx)];
    __syncthreads();
    g_Wt[(size_t)(n0 + ty) * MP + (k0 + tx)] = __float2half_rn(t[tx][ty]);
}

// ---------------------------------------------------------------------------
// Kernel 1: K[i,j] = exp(-sqrt(max(xsq+zsq-2*X.Z, 0))/bw), stored fp16.
// NT GEMM, fp16 m16n8k16, BM=BN=128, BK=32 halves, double-buffered.
// 8 warps, warp tile 64x32. Grid (64, 157).
// ---------------------------------------------------------------------------
__global__ __launch_bounds__(256, 2)
void laplace_gemm_kernel(const float* __restrict__ X, const float* __restrict__ Z,
                         const void* __restrict__ bwp) {
    __shared__ uint32_t Xs[2][128][PADW];   // 16 data words (32 halves) + 4 pad
    __shared__ uint32_t Zs[2][128][PADW];

    const int bm = blockIdx.x;      // 0..63
    const int bn = blockIdx.y;      // 0..156
    const int tid = threadIdx.x;
    const int lane = tid & 31;
    const int wid = tid >> 5;
    const int wm = (wid & 1) * 64;
    const int wn = (wid >> 1) * 32;

    float acc[4][4][4];
#pragma unroll
    for (int mt = 0; mt < 4; mt++)
#pragma unroll
        for (int nt = 0; nt < 4; nt++)
#pragma unroll
            for (int i = 0; i < 4; i++) acc[mt][nt][i] = 0.f;

    // Staging: thread covers one 16-float half-row of X and of Z per tile.
    const int lr = tid >> 1;               // 0..127
    const int fs = (tid & 1) * 16;         // float offset within 32-float k-chunk
    const int wo = (tid & 1) * 8;          // word offset in smem row
    const size_t xg = (size_t)(bm * 128 + lr) * DD + fs;
    const int zr = bn * 128 + lr;
    const bool zok = (zr < MC);
    const size_t zg = (size_t)zr * DD + fs;

    uint32_t pw[16];   // packed halves: [0..7] X, [8..15] Z

    // Prologue: load+convert tile 0
#pragma unroll
    for (int j = 0; j < 4; j++) {
        float4 v = *(const float4*)(X + xg + j * 4);
        pw[j * 2]     = h2u(__floats2half2_rn(v.x, v.y));
        pw[j * 2 + 1] = h2u(__floats2half2_rn(v.z, v.w));
    }
#pragma unroll
    for (int j = 0; j < 4; j++) {
        float4 v = zok ? *(const float4*)(Z + zg + j * 4) : make_float4(0.f, 0.f, 0.f, 0.f);
        pw[8 + j * 2]     = h2u(__floats2half2_rn(v.x, v.y));
        pw[8 + j * 2 + 1] = h2u(__floats2half2_rn(v.z, v.w));
    }
    *(uint4*)&Xs[0][lr][wo]     = *(uint4*)&pw[0];
    *(uint4*)&Xs[0][lr][wo + 4] = *(uint4*)&pw[4];
    *(uint4*)&Zs[0][lr][wo]     = *(uint4*)&pw[8];
    *(uint4*)&Zs[0][lr][wo + 4] = *(uint4*)&pw[12];
    __syncthreads();

    const int KT = DD / 32;   // 32
    for (int kt = 0; kt < KT; kt++) {
        const int buf = kt & 1;
        if (kt + 1 < KT) {
            const size_t off = (size_t)(kt + 1) * 32;
#pragma unroll
            for (int j = 0; j < 4; j++) {
                float4 v = *(const float4*)(X + xg + off + j * 4);
                pw[j * 2]     = h2u(__floats2half2_rn(v.x, v.y));
                pw[j * 2 + 1] = h2u(__floats2half2_rn(v.z, v.w));
            }
#pragma unroll
            for (int j = 0; j < 4; j++) {
                float4 v = zok ? *(const float4*)(Z + zg + off + j * 4)
                               : make_float4(0.f, 0.f, 0.f, 0.f);
                pw[8 + j * 2]     = h2u(__floats2half2_rn(v.x, v.y));
                pw[8 + j * 2 + 1] = h2u(__floats2half2_rn(v.z, v.w));
            }
        }

#pragma unroll
        for (int kk = 0; kk < 2; kk++) {
            const int kw = kk * 8 + (lane & 3);
            const int frow = lane >> 2;
            uint32_t a[4][4], b[4][2];
#pragma unroll
            for (int mt = 0; mt < 4; mt++) {
                int r = wm + mt * 16 + frow;
                a[mt][0] = Xs[buf][r][kw];
                a[mt][1] = Xs[buf][r + 8][kw];
                a[mt][2] = Xs[buf][r][kw + 4];
                a[mt][3] = Xs[buf][r + 8][kw + 4];
            }
#pragma unroll
            for (int nt = 0; nt < 4; nt++) {
                int c = wn + nt * 8 + frow;
                b[nt][0] = Zs[buf][c][kw];
                b[nt][1] = Zs[buf][c][kw + 4];
            }
#pragma unroll
            for (int mt = 0; mt < 4; mt++)
#pragma unroll
                for (int nt = 0; nt < 4; nt++)
                    mma_f16(acc[mt][nt], a[mt], b[nt]);
        }

        if (kt + 1 < KT) {
            const int nb = buf ^ 1;
            *(uint4*)&Xs[nb][lr][wo]     = *(uint4*)&pw[0];
            *(uint4*)&Xs[nb][lr][wo + 4] = *(uint4*)&pw[4];
            *(uint4*)&Zs[nb][lr][wo]     = *(uint4*)&pw[8];
            *(uint4*)&Zs[nb][lr][wo + 4] = *(uint4*)&pw[12];
        }
        __syncthreads();
    }

    // Epilogue: d2 -> exp(-d/bw) -> g_K (fp16)
    const float inv_bw = 1.0f / resolve_bw(bwp);
#pragma unroll
    for (int mt = 0; mt < 4; mt++) {
        const int r0 = bm * 128 + wm + mt * 16 + (lane >> 2);
        const float xs0 = g_xsq[r0];
        const float xs1 = g_xsq[r0 + 8];
#pragma unroll
        for (int nt = 0; nt < 4; nt++) {
            const int c0 = bn * 128 + wn + nt * 8 + ((lane & 3) << 1);
            const float zs0 = g_zsq[c0];
            const float zs1 = g_zsq[c0 + 1];
            float f0 = __expf(-sqrtf(fmaxf(xs0 + zs0 - 2.f * acc[mt][nt][0], 0.f)) * inv_bw);
            float f1 = __expf(-sqrtf(fmaxf(xs0 + zs1 - 2.f * acc[mt][nt][1], 0.f)) * inv_bw);
            *(__half2*)&g_K[(size_t)r0 * MP + c0] = __floats2half2_rn(f0, f1);
            f0 = __expf(-sqrtf(fmaxf(xs1 + zs0 - 2.f * acc[mt][nt][2], 0.f)) * inv_bw);
            f1 = __expf(-sqrtf(fmaxf(xs1 + zs1 - 2.f * acc[mt][nt][3], 0.f)) * inv_bw);
            *(__half2*)&g_K[(size_t)(r0 + 8) * MP + c0] = __floats2half2_rn(f0, f1);
        }
    }
}

// ---------------------------------------------------------------------------
// Kernel 2: pred = K @ W  (NT: A=g_K fp16 [NQ,MP], B=g_Wt fp16 [YY,MP]).
// BM=64, BN=128, BK=32 -> grid (128, 2) = 256 CTAs. Warp tile 32x32.
// Tail k in [MC, MP): K garbage x Wt zero = 0.
// ---------------------------------------------------------------------------
__global__ __launch_bounds__(256, 2)
void wgemm_kernel(float* __restrict__ out) {
    __shared__ uint32_t As[2][64][PADW];
    __shared__ uint32_t Bs[2][128][PADW];

    const int bm = blockIdx.x;   // 0..127
    const int bn = blockIdx.y;   // 0..1
    const int tid = threadIdx.x;
    const int lane = tid & 31;
    const int wid = tid >> 5;
    const int wm = (wid & 1) * 32;
    const int wn = (wid >> 1) * 32;

    float acc[2][4][4];
#pragma unroll
    for (int mt = 0; mt < 2; mt++)
#pragma unroll
        for (int nt = 0; nt < 4; nt++)
#pragma unroll
            for (int i = 0; i < 4; i++) acc[mt][nt][i] = 0.f;

    // A staging: 64 rows x 16 words; thread: row tid>>2, words (tid&3)*4 (1 uint4)
    const int alr = tid >> 2;
    const int awo = (tid & 3) * 4;
    const size_t abase = (size_t)(bm * 64 + alr) * MP + awo * 2;   // halves
    // B staging: 128 rows x 16 words; thread: row tid>>1, words (tid&1)*8 (2 uint4)
    const int blr = tid >> 1;
    const int bwo = (tid & 1) * 8;
    const size_t bbase = (size_t)blr * MP + bwo * 2;
    const size_t bcol = (size_t)bn * 128 * MP;   // Wt row block for this bn

    // Prologue
    {
        uint4 ua = *(const uint4*)(g_K + abase);
        uint4 ub0 = *(const uint4*)(g_Wt + bcol + bbase);
        uint4 ub1 = *(const uint4*)(g_Wt + bcol + bbase + 8);
        *(uint4*)&As[0][alr][awo] = ua;
        *(uint4*)&Bs[0][blr][bwo] = ub0;
        *(uint4*)&Bs[0][blr][bwo + 4] = ub1;
    }
    __syncthreads();

    const int KT = MP / 32;   // 628
    for (int kt = 0; kt < KT; kt++) {
        const int buf = kt & 1;
        uint4 ua, ub0, ub1;
        if (kt + 1 < KT) {
            const size_t off = (size_t)(kt + 1) * 32;
            ua  = *(const uint4*)(g_K + abase + off);
            ub0 = *(const uint4*)(g_Wt + bcol + bbase + off);
            ub1 = *(const uint4*)(g_Wt + bcol + bbase + off + 8);
        }

#pragma unroll
        for (int kk = 0; kk < 2; kk++) {
            const int kw = kk * 8 + (lane & 3);
            const int frow = lane >> 2;
            uint32_t a[2][4], b[4][2];
#pragma unroll
            for (int mt = 0; mt < 2; mt++) {
                int r = wm + mt * 16 + frow;
                a[mt][0] = As[buf][r][kw];
                a[mt][1] = As[buf][r + 8][kw];
                a[mt][2] = As[buf][r][kw + 4];
                a[mt][3] = As[buf][r + 8][kw + 4];
            }
#pragma unroll
            for (int nt = 0; nt < 4; nt++) {
                int c = wn + nt * 8 + frow;
                b[nt][0] = Bs[buf][c][kw];
                b[nt][1] = Bs[buf][c][kw + 4];
            }
#pragma unroll
            for (int mt = 0; mt < 2; mt++)
#pragma unroll
                for (int nt = 0; nt < 4; nt++)
                    mma_f16(acc[mt][nt], a[mt], b[nt]);
        }

        if (kt + 1 < KT) {
            const int nb = buf ^ 1;
            *(uint4*)&As[nb][alr][awo] = ua;
            *(uint4*)&Bs[nb][blr][bwo] = ub0;
            *(uint4*)&Bs[nb][blr][bwo + 4] = ub1;
        }
        __syncthreads();
    }

#pragma unroll
    for (int mt = 0; mt < 2; mt++) {
        const int r0 = bm * 64 + wm + mt * 16 + (lane >> 2);
#pragma unroll
        for (int nt = 0; nt < 4; nt++) {
            const int c0 = bn * 128 + wn + nt * 8 + ((lane & 3) << 1);
            *(float2*)(out + (size_t)r0 * YY + c0) =
                make_float2(acc[mt][nt][0], acc[mt][nt][1]);
            *(float2*)(out + (size_t)(r0 + 8) * YY + c0) =
                make_float2(acc[mt][nt][2], acc[mt][nt][3]);
        }
    }
}

// ---------------------------------------------------------------------------
// Entry point (graph-capturable: launches only)
// ---------------------------------------------------------------------------
extern "C" void kernel_launch(void* const* d_in, const int* in_sizes, int n_in,
                              void* d_out, int out_size) {
    const float* batch   = (const float*)d_in[0];
    const float* centers = (const float*)d_in[1];
    const float* weight  = (const float*)d_in[2];
    const void*  bwp     = d_in[3];

    {
        int warps = NQ + MC;
        int blocks = (warps * 32 + 255) / 256;
        rowsq_kernel<<<blocks, 256>>>(batch, centers);
    }
    {
        dim3 grid(MC / 32, YY / 32);            // (625, 8)
        wtrans_kernel<<<grid, dim3(32, 32)>>>(weight);
    }
    {
        dim3 grid(NQ / 128, (MC + 127) / 128);  // (64, 157)
        laplace_gemm_kernel<<<grid, 256>>>(batch, centers, bwp);
    }
    {
        dim3 grid(NQ / 64, YY / 128);           // (128, 2)
        wgemm_kernel<<<grid, 256>>>((float*)d_out);
    }
}